// round 1
// baseline (speedup 1.0000x reference)
#include <cuda_runtime.h>
#include <cuda_bf16.h>

// Problem constants
#define BB 32
#define NN 128
#define HH 128
#define HD 256
#define NHEADS 4
#define DH 64

// Scratch layout (floats)
#define OFF_BASE 0u
#define OFF_X0   524288u
#define OFF_Q    1048576u
#define OFF_K    2097152u
#define OFF_V    3145728u
#define OFF_S    4194304u
#define OFF_X1   5242880u
#define OFF_X2   6291456u
#define SCRATCH_TOTAL 7340032u

__device__ float g_scratch[SCRATCH_TOTAL];

// ---------------------------------------------------------------------------
// Kernel 1: base[b,s,j] = node/emb part of msg @ W1 + b1  (t-independent part)
// ---------------------------------------------------------------------------
__global__ void k_base(const float* __restrict__ nf, const int* __restrict__ et,
                       const float* __restrict__ emb, const float* __restrict__ W1,
                       const float* __restrict__ b1) {
    int bn = blockIdx.x;       // b*N+s
    int j  = threadIdx.x;      // 0..127
    const float* f = nf + bn * 9;
    const float* em = emb + et[bn] * 8;
    float acc = b1[j];
#pragma unroll
    for (int i = 0; i < 9; i++) acc += f[i] * W1[i * HH + j];
#pragma unroll
    for (int i = 0; i < 8; i++) acc += em[i] * W1[(9 + i) * HH + j];
    g_scratch[OFF_BASE + bn * HH + j] = acc;
}

// ---------------------------------------------------------------------------
// Kernel 2 (heavy): per (b, t-tile): loop s, build h1 row = LN(relu(base+a*w17)),
// GEMM row @ Wh, relu, LN, masked-accumulate into x0[b,t,:].
// Masked (s,t) rows are skipped entirely (~50% of work).
// ---------------------------------------------------------------------------
#define TT 16
#define EMBED_SMEM ((16384 + 128 + TT * 128 + 2 * TT) * 4)

__global__ void k_embed(const float* __restrict__ adj, const float* __restrict__ W1,
                        const float* __restrict__ g1, const float* __restrict__ be1,
                        const float* __restrict__ Wh, const float* __restrict__ bh,
                        const float* __restrict__ gh, const float* __restrict__ beh) {
    extern __shared__ float sm[];
    float* sWh   = sm;                 // 128*128
    float* sBase = sWh + 16384;        // 128
    float* sH1   = sBase + 128;        // TT*128
    float* sA    = sH1 + TT * 128;     // TT (masked adj value)
    float* sM    = sA + TT;            // TT (mask as float)

    int tid = threadIdx.x;             // 256 threads
    int b = blockIdx.y, t0 = blockIdx.x * TT;
    int row = tid >> 4, cg = tid & 15, col0 = cg * 8;
    unsigned gmask = 0xFFFFu << (tid & 16);

    for (int idx = tid; idx < 16384; idx += 256) sWh[idx] = Wh[idx];

    float w17v[8], g1v[8], be1v[8], ghv[8], behv[8], bhv[8], acc[8];
#pragma unroll
    for (int u = 0; u < 8; u++) {
        int j = col0 + u;
        w17v[u] = W1[17 * HH + j];
        g1v[u] = g1[j]; be1v[u] = be1[j];
        ghv[u] = gh[j]; behv[u] = beh[j]; bhv[u] = bh[j];
        acc[u] = 0.f;
    }

    for (int s = 0; s < NN; s++) {
        __syncthreads();
        if (tid < 128) sBase[tid] = g_scratch[OFF_BASE + (b * NN + s) * HH + tid];
        if (tid >= 128 && tid < 128 + TT) {
            int i = tid - 128;
            float a = adj[(b * NN + s) * NN + t0 + i];
            bool m = (a > 0.f) && (a < 1.0f);
            sA[i] = m ? a : 0.f;
            sM[i] = m ? 1.f : 0.f;
        }
        __syncthreads();

        bool active = sM[row] > 0.5f;
        if (active) {
            float a = sA[row];
            float y[8]; float sum = 0.f, ss = 0.f;
#pragma unroll
            for (int u = 0; u < 8; u++) {
                float v = fmaxf(sBase[col0 + u] + a * w17v[u], 0.f);
                y[u] = v; sum += v; ss += v * v;
            }
#pragma unroll
            for (int o = 8; o >= 1; o >>= 1) {
                sum += __shfl_xor_sync(gmask, sum, o);
                ss  += __shfl_xor_sync(gmask, ss, o);
            }
            float mean = sum * (1.f / 128.f);
            float var = ss * (1.f / 128.f) - mean * mean;
            float rs = rsqrtf(var + 1e-5f);
#pragma unroll
            for (int u = 0; u < 8; u++)
                sH1[row * 128 + col0 + u] = (y[u] - mean) * rs * g1v[u] + be1v[u];
        }
        __syncthreads();

        if (active) {
            float t8[8];
#pragma unroll
            for (int u = 0; u < 8; u++) t8[u] = bhv[u];
            const float* hrow = sH1 + row * 128;
#pragma unroll 4
            for (int kk = 0; kk < 128; kk++) {
                float hv = hrow[kk];
                const float4* w4 = (const float4*)(sWh + kk * 128 + col0);
                float4 w0 = w4[0], w1 = w4[1];
                t8[0] += hv * w0.x; t8[1] += hv * w0.y;
                t8[2] += hv * w0.z; t8[3] += hv * w0.w;
                t8[4] += hv * w1.x; t8[5] += hv * w1.y;
                t8[6] += hv * w1.z; t8[7] += hv * w1.w;
            }
            float sum = 0.f, ss = 0.f;
#pragma unroll
            for (int u = 0; u < 8; u++) {
                float v = fmaxf(t8[u], 0.f);
                t8[u] = v; sum += v; ss += v * v;
            }
#pragma unroll
            for (int o = 8; o >= 1; o >>= 1) {
                sum += __shfl_xor_sync(gmask, sum, o);
                ss  += __shfl_xor_sync(gmask, ss, o);
            }
            float mean = sum * (1.f / 128.f);
            float var = ss * (1.f / 128.f) - mean * mean;
            float rs = rsqrtf(var + 1e-5f);
#pragma unroll
            for (int u = 0; u < 8; u++)
                acc[u] += (t8[u] - mean) * rs * ghv[u] + behv[u];
        }
    }

    int t = t0 + row;
#pragma unroll
    for (int u = 0; u < 8; u++)
        g_scratch[OFF_X0 + (b * NN + t) * HH + col0 + u] = acc[u];
}

// ---------------------------------------------------------------------------
// Kernel 3: fused q/k/v/skip projections. 8 rows per block, 256 cols = threads.
// ---------------------------------------------------------------------------
template <int HIN>
__global__ void k_proj(unsigned xoff,
                       const float* __restrict__ Wq, const float* __restrict__ bq,
                       const float* __restrict__ Wk, const float* __restrict__ bk,
                       const float* __restrict__ Wv, const float* __restrict__ bv,
                       const float* __restrict__ Ws, const float* __restrict__ bs) {
    __shared__ float sX[8][HIN];
    const float* x = g_scratch + xoff;
    int r0 = blockIdx.x * 8;
    int tid = threadIdx.x; // 256
    for (int idx = tid; idx < 8 * HIN; idx += 256) {
        int r = idx / HIN, i = idx % HIN;
        sX[r][i] = x[(r0 + r) * HIN + i];
    }
    __syncthreads();
    int j = tid;
    float aq[8], ak[8], av[8], as_[8];
    float bqv = bq[j], bkv = bk[j], bvv = bv[j], bsv = bs[j];
#pragma unroll
    for (int r = 0; r < 8; r++) { aq[r] = bqv; ak[r] = bkv; av[r] = bvv; as_[r] = bsv; }
    for (int i = 0; i < HIN; i++) {
        float wq = Wq[i * HD + j], wk = Wk[i * HD + j];
        float wv = Wv[i * HD + j], ws = Ws[i * HD + j];
#pragma unroll
        for (int r = 0; r < 8; r++) {
            float xv = sX[r][i];
            aq[r] += xv * wq; ak[r] += xv * wk;
            av[r] += xv * wv; as_[r] += xv * ws;
        }
    }
#pragma unroll
    for (int r = 0; r < 8; r++) {
        unsigned o = (unsigned)(r0 + r) * HD + j;
        g_scratch[OFF_Q + o] = aq[r];
        g_scratch[OFF_K + o] = ak[r];
        g_scratch[OFF_V + o] = av[r];
        g_scratch[OFF_S + o] = as_[r];
    }
}

// ---------------------------------------------------------------------------
// Kernel 4: attention. Block = (b, h, tile of 8 t's). 128 threads.
// ---------------------------------------------------------------------------
#define TB 8
__global__ void k_attn(const float* __restrict__ adj, const float* __restrict__ we,
                       unsigned outoff) {
    __shared__ float sK[128][65];
    __shared__ float sQ[TB][64];
    __shared__ float sW[TB][128];
    __shared__ float sB[TB];
    __shared__ float sQE[TB];
    __shared__ float redA[4], redB[4], redC[4];
    __shared__ float sPart[TB][64];

    int b = blockIdx.z, h = blockIdx.y, t0 = blockIdx.x * TB;
    int tid = threadIdx.x; // 128
    const float* q = g_scratch + OFF_Q;
    const float* k = g_scratch + OFF_K;
    const float* v = g_scratch + OFF_V;
    const float* skip = g_scratch + OFF_S;
    float* xout = g_scratch + outoff;

    for (int idx = tid; idx < 128 * 64; idx += 128) {
        int s = idx >> 6, d = idx & 63;
        sK[s][d] = k[((b * NN + s) * NHEADS + h) * DH + d];
    }
    for (int idx = tid; idx < TB * 64; idx += 128) {
        int u = idx >> 6, d = idx & 63;
        sQ[u][d] = q[((b * NN + t0 + u) * NHEADS + h) * DH + d];
    }
    __syncthreads();

    { // qe[u] = q_t . we_h
        int u = tid >> 4, l = tid & 15;
        float p = 0.f;
#pragma unroll
        for (int c = 0; c < 4; c++) { int d = l + 16 * c; p += sQ[u][d] * we[h * DH + d]; }
        unsigned gm = 0xFFFFu << (tid & 16);
#pragma unroll
        for (int o = 8; o >= 1; o >>= 1) p += __shfl_xor_sync(gm, p, o);
        if (l == 0) sQE[u] = p;
    }
    __syncthreads();

    const float scale = 0.125f;
    int s = tid, lane = tid & 31, wid = tid >> 5;
    for (int u = 0; u < TB; u++) {
        int t = t0 + u;
        float a = adj[(b * NN + s) * NN + t];
        bool m = (a > 0.f) && (a < 1.0f);
        float av_ = m ? a : 0.f;
        float dot = 0.f;
#pragma unroll
        for (int d = 0; d < 64; d++) dot += sK[s][d] * sQ[u][d];
        float logit = m ? (dot + av_ * sQE[u]) * scale : -1e30f;
        float mx = logit;
#pragma unroll
        for (int o = 16; o >= 1; o >>= 1) mx = fmaxf(mx, __shfl_xor_sync(0xffffffffu, mx, o));
        if (lane == 0) redA[wid] = mx;
        __syncthreads();
        mx = fmaxf(fmaxf(redA[0], redA[1]), fmaxf(redA[2], redA[3]));
        float w = m ? __expf(logit - mx) : 0.f;
        float wa = w * av_;
        float sw = w, swa = wa;
#pragma unroll
        for (int o = 16; o >= 1; o >>= 1) {
            sw  += __shfl_xor_sync(0xffffffffu, sw, o);
            swa += __shfl_xor_sync(0xffffffffu, swa, o);
        }
        if (lane == 0) { redB[wid] = sw; redC[wid] = swa; }
        __syncthreads();
        float den = redB[0] + redB[1] + redB[2] + redB[3];
        float SWA = redC[0] + redC[1] + redC[2] + redC[3];
        float inv = 1.f / fmaxf(den, 1e-16f);
        sW[u][s] = w * inv;
        if (tid == 0) sB[u] = SWA * inv;
        __syncthreads();
    }

    // out[t,d] = sum_s alpha * v  (+ beta*we + skip, relu)
    int d = tid & 63, half = tid >> 6;
    float o8[TB];
#pragma unroll
    for (int u = 0; u < TB; u++) o8[u] = 0.f;
    for (int s2 = half * 64; s2 < half * 64 + 64; s2++) {
        float vv = v[((b * NN + s2) * NHEADS + h) * DH + d];
#pragma unroll
        for (int u = 0; u < TB; u++) o8[u] += sW[u][s2] * vv;
    }
    if (half == 1) {
#pragma unroll
        for (int u = 0; u < TB; u++) sPart[u][d] = o8[u];
    }
    __syncthreads();
    if (half == 0) {
        float wev = we[h * DH + d];
#pragma unroll
        for (int u = 0; u < TB; u++) {
            int t = t0 + u;
            unsigned idx = (unsigned)(b * NN + t) * HD + h * DH + d;
            float res = o8[u] + sPart[u][d] + sB[u] * wev + skip[idx];
            xout[idx] = fmaxf(res, 0.f);
        }
    }
}

// ---------------------------------------------------------------------------
// Kernel 5: gather agent rows
// ---------------------------------------------------------------------------
__global__ void k_gather(const int* __restrict__ agent, float* __restrict__ out) {
    int b = blockIdx.x, j = threadIdx.x; // 256
    out[b * HD + j] = g_scratch[OFF_X2 + (unsigned)(b * NN + agent[b]) * HD + j];
}

// ---------------------------------------------------------------------------
extern "C" void kernel_launch(void* const* d_in, const int* in_sizes, int n_in,
                              void* d_out, int out_size) {
    const float* node_feat = (const float*)d_in[0];
    const int*   entity_type = (const int*)d_in[1];
    const float* adj = (const float*)d_in[2];
    const int*   agent_id = (const int*)d_in[3];
    const float* emb = (const float*)d_in[4];
    const float* W1 = (const float*)d_in[5];
    const float* b1 = (const float*)d_in[6];
    const float* g1 = (const float*)d_in[7];
    const float* be1 = (const float*)d_in[8];
    const float* Wh = (const float*)d_in[9];
    const float* bh = (const float*)d_in[10];
    const float* gh = (const float*)d_in[11];
    const float* beh = (const float*)d_in[12];
    const float* Wq1 = (const float*)d_in[13];
    const float* bq1 = (const float*)d_in[14];
    const float* Wk1 = (const float*)d_in[15];
    const float* bk1 = (const float*)d_in[16];
    const float* Wv1 = (const float*)d_in[17];
    const float* bv1 = (const float*)d_in[18];
    const float* We1 = (const float*)d_in[19];
    const float* Ws1 = (const float*)d_in[20];
    const float* bs1 = (const float*)d_in[21];
    const float* Wq2 = (const float*)d_in[22];
    const float* bq2 = (const float*)d_in[23];
    const float* Wk2 = (const float*)d_in[24];
    const float* bk2 = (const float*)d_in[25];
    const float* Wv2 = (const float*)d_in[26];
    const float* bv2 = (const float*)d_in[27];
    const float* We2 = (const float*)d_in[28];
    const float* Ws2 = (const float*)d_in[29];
    const float* bs2 = (const float*)d_in[30];

    cudaFuncSetAttribute(k_embed, cudaFuncAttributeMaxDynamicSharedMemorySize, EMBED_SMEM);

    k_base<<<BB * NN, 128>>>(node_feat, entity_type, emb, W1, b1);
    k_embed<<<dim3(NN / TT, BB), 256, EMBED_SMEM>>>(adj, W1, g1, be1, Wh, bh, gh, beh);

    // tconv layer 1 (input H=128 -> x1)
    k_proj<128><<<(BB * NN) / 8, 256>>>(OFF_X0, Wq1, bq1, Wk1, bk1, Wv1, bv1, Ws1, bs1);
    k_attn<<<dim3(NN / TB, NHEADS, BB), 128>>>(adj, We1, OFF_X1);

    // tconv layer 2 (input HD=256 -> x2)
    k_proj<256><<<(BB * NN) / 8, 256>>>(OFF_X1, Wq2, bq2, Wk2, bk2, Wv2, bv2, Ws2, bs2);
    k_attn<<<dim3(NN / TB, NHEADS, BB), 128>>>(adj, We2, OFF_X2);

    k_gather<<<BB, 256>>>(agent_id, (float*)d_out);
}

// round 3
// speedup vs baseline: 1.7623x; 1.7623x over previous
#include <cuda_runtime.h>
#include <cuda_bf16.h>
#include <cstdint>

// Problem constants
#define BB 32
#define NN 128
#define HH 128
#define HD 256
#define NHEADS 4
#define DH 64

// Scratch layout (floats)
#define OFF_BASE 0u
#define OFF_X0   524288u
#define OFF_Q    1048576u
#define OFF_K    2097152u
#define OFF_V    3145728u
#define OFF_S    4194304u
#define OFF_X1   5242880u
#define OFF_X2   6291456u
#define OFF_PART 7340032u   // 4 * 32 * 128 * 128 floats
#define OFF_CNT  9437184u   // 4 * 32 * 128 floats
#define SCRATCH_TOTAL 9453568u

__device__ float g_scratch[SCRATCH_TOTAL];

// ---------------------------------------------------------------------------
// PTX helpers (generic sm_80+ instructions only — no sm_103a-specific ops)
// ---------------------------------------------------------------------------
__device__ __forceinline__ uint32_t smem_u32(const void* p) {
    uint32_t a;
    asm("{ .reg .u64 t; cvta.to.shared.u64 t, %1; cvt.u32.u64 %0, t; }" : "=r"(a) : "l"(p));
    return a;
}
__device__ __forceinline__ void ldsm_x4(uint32_t& r0, uint32_t& r1, uint32_t& r2, uint32_t& r3, uint32_t addr) {
    asm volatile("ldmatrix.sync.aligned.m8n8.x4.shared.b16 {%0,%1,%2,%3}, [%4];"
                 : "=r"(r0), "=r"(r1), "=r"(r2), "=r"(r3) : "r"(addr));
}
__device__ __forceinline__ void mma_bf16(float* c, const uint32_t* a, uint32_t b0, uint32_t b1) {
    asm volatile("mma.sync.aligned.m16n8k16.row.col.f32.bf16.bf16.f32 "
                 "{%0,%1,%2,%3}, {%4,%5,%6,%7}, {%8,%9}, {%0,%1,%2,%3};"
                 : "+f"(c[0]), "+f"(c[1]), "+f"(c[2]), "+f"(c[3])
                 : "r"(a[0]), "r"(a[1]), "r"(a[2]), "r"(a[3]), "r"(b0), "r"(b1));
}

// ---------------------------------------------------------------------------
// Kernel 1: base[b,s,j] = node/emb part of msg @ W1 + b1  (t-independent part)
// ---------------------------------------------------------------------------
__global__ void k_base(const float* __restrict__ nf, const int* __restrict__ et,
                       const float* __restrict__ emb, const float* __restrict__ W1,
                       const float* __restrict__ b1) {
    int bn = blockIdx.x;
    int j  = threadIdx.x;
    const float* f = nf + bn * 9;
    const float* em = emb + et[bn] * 8;
    float acc = b1[j];
#pragma unroll
    for (int i = 0; i < 9; i++) acc += f[i] * W1[i * HH + j];
#pragma unroll
    for (int i = 0; i < 8; i++) acc += em[i] * W1[(9 + i) * HH + j];
    g_scratch[OFF_BASE + bn * HH + j] = acc;
}

// ---------------------------------------------------------------------------
// Kernel 2 (HMMA): per (b, s-chunk of 32): build A = h1 (all 128 t) as bf16
// hi/lo, warp-level mma.sync vs resident Wh^T hi/lo, epilogue +bh, relu, LN
// (affine hoisted), masked accumulation in fragment-layout registers.
// ---------------------------------------------------------------------------
#define PK 136                                // SMEM pitch (bf16 elems), 272B rows
#define SM_BASE 0
#define SM_W17  512
#define SM_G1   1024
#define SM_BE1  1536
#define SM_BH   2048
#define SM_MASK 2560
#define SM_AHI  4096
#define SM_ALO  (SM_AHI + 128 * PK * 2)       // +34816
#define SM_BHI  (SM_ALO + 128 * PK * 2)
#define SM_BLO  (SM_BHI + 128 * PK * 2)
#define EMB_SMEM (SM_BLO + 128 * PK * 2)      // 143360 bytes

__global__ void __launch_bounds__(256, 1)
k_embed_mma(const float* __restrict__ adj, const float* __restrict__ W1,
            const float* __restrict__ g1, const float* __restrict__ be1,
            const float* __restrict__ Wh, const float* __restrict__ bh) {
    extern __shared__ char sm[];
    uint32_t smb = smem_u32(sm);
    float* sBase = (float*)(sm + SM_BASE);
    float* sW17  = (float*)(sm + SM_W17);
    float* sG1   = (float*)(sm + SM_G1);
    float* sBe1  = (float*)(sm + SM_BE1);
    float* sBh   = (float*)(sm + SM_BH);
    float* sMask = (float*)(sm + SM_MASK);

    int tid = threadIdx.x;                 // 256
    int lane = tid & 31, wid = tid >> 5;   // 8 warps
    int chunk = blockIdx.x, b = blockIdx.y;

    if (tid < 128) {
        sW17[tid] = W1[17 * HH + tid];
        sG1[tid]  = g1[tid];
        sBe1[tid] = be1[tid];
        sBh[tid]  = bh[tid];
    }

    // B = Wh^T as [j][k], hi/lo bf16, padded pitch
    for (int idx = tid; idx < 16384; idx += 256) {
        int k = idx >> 7, j = idx & 127;
        float w = Wh[idx];
        __nv_bfloat16 h = __float2bfloat16(w);
        __nv_bfloat16 l = __float2bfloat16(w - __bfloat162float(h));
        *(__nv_bfloat16*)(sm + SM_BHI + (j * PK + k) * 2) = h;
        *(__nv_bfloat16*)(sm + SM_BLO + (j * PK + k) * 2) = l;
    }

    // A-build thread mapping: thread = 2*t + half, half covers 64 cols
    int tA = tid >> 1, half = tid & 1;

    // MMA row ownership: warp wid owns rows m0..m0+15 (r0 = m0+lane/4, r1 = r0+8)
    int m0 = wid * 16;
    int r0 = m0 + (lane >> 2), r1 = r0 + 8;

    float accS[64];   // masked normalized accumulation, fragment layout
#pragma unroll
    for (int u = 0; u < 64; u++) accS[u] = 0.f;
    float cnt0 = 0.f, cnt1 = 0.f;

    int s0 = chunk * 32;
    for (int si = 0; si < 32; si++) {
        int s = s0 + si;

        __syncthreads();   // previous iter's ldmatrix/epilogue reads done
        if (tid < 128) sBase[tid] = g_scratch[OFF_BASE + (b * NN + s) * HH + tid];
        {
            float araw = adj[(b * NN + s) * NN + tA];
            bool mk = (araw > 0.f) && (araw < 1.0f);
            if (half == 0) sMask[tA] = mk ? 1.f : 0.f;
        }
        __syncthreads();

        // ---- Build A row tA, cols [half*64, half*64+64) ----
        {
            float araw = adj[(b * NN + s) * NN + tA];
            bool mk = (araw > 0.f) && (araw < 1.0f);
            float at = mk ? araw : 0.f;
            int c0 = half * 64;
            float sum = 0.f, ssum = 0.f;
#pragma unroll 4
            for (int j = 0; j < 64; j++) {
                float y = fmaxf(sBase[c0 + j] + at * sW17[c0 + j], 0.f);
                sum += y; ssum += y * y;
            }
            sum  += __shfl_xor_sync(0xffffffffu, sum, 1);
            ssum += __shfl_xor_sync(0xffffffffu, ssum, 1);
            float mean = sum * (1.f / 128.f);
            float rs = rsqrtf(ssum * (1.f / 128.f) - mean * mean + 1e-5f);
#pragma unroll 2
            for (int j2 = 0; j2 < 32; j2++) {
                int j = c0 + j2 * 2;
                float y0 = fmaxf(sBase[j] + at * sW17[j], 0.f);
                float y1 = fmaxf(sBase[j + 1] + at * sW17[j + 1], 0.f);
                float h0 = (y0 - mean) * rs * sG1[j] + sBe1[j];
                float h1 = (y1 - mean) * rs * sG1[j + 1] + sBe1[j + 1];
                __nv_bfloat16 a0 = __float2bfloat16(h0), a1 = __float2bfloat16(h1);
                __nv_bfloat16 b0 = __float2bfloat16(h0 - __bfloat162float(a0));
                __nv_bfloat16 b1 = __float2bfloat16(h1 - __bfloat162float(a1));
                uint32_t hiw = (uint32_t)__bfloat16_as_ushort(a0) | ((uint32_t)__bfloat16_as_ushort(a1) << 16);
                uint32_t low = (uint32_t)__bfloat16_as_ushort(b0) | ((uint32_t)__bfloat16_as_ushort(b1) << 16);
                uint32_t off = (uint32_t)(tA * PK + j) * 2;
                *(uint32_t*)(sm + SM_AHI + off) = hiw;
                *(uint32_t*)(sm + SM_ALO + off) = low;
            }
        }
        __syncthreads();

        // ---- MMA: D[16 x 128] per warp, 3-term bf16 split ----
        float c[64];
#pragma unroll
        for (int u = 0; u < 64; u++) c[u] = 0.f;

        // A frag address: threads 0-15 -> rows m0+i, k0; 16-31 -> rows m0+(i-16), k0+8
        uint32_t aoff = (uint32_t)((m0 + (lane & 15)) * PK + (lane >> 4) * 8) * 2;
        // B pair address: rows = n, col groups per ldmatrix x4 (2 n-tiles at once)
        uint32_t brow = (uint32_t)(((lane & 16) >> 1) + (lane & 7));
        uint32_t bk   = (uint32_t)(((lane >> 3) & 1) * 8);

#pragma unroll
        for (int kk = 0; kk < 8; kk++) {
            uint32_t ah[4], al[4];
            uint32_t ka = aoff + (uint32_t)(kk * 16) * 2;
            ldsm_x4(ah[0], ah[1], ah[2], ah[3], smb + SM_AHI + ka);
            ldsm_x4(al[0], al[1], al[2], al[3], smb + SM_ALO + ka);
#pragma unroll
            for (int jp = 0; jp < 8; jp++) {
                uint32_t boff = (uint32_t)((jp * 16 + brow) * PK + kk * 16 + bk) * 2;
                uint32_t bh4[4], bl4[4];
                ldsm_x4(bh4[0], bh4[1], bh4[2], bh4[3], smb + SM_BHI + boff);
                ldsm_x4(bl4[0], bl4[1], bl4[2], bl4[3], smb + SM_BLO + boff);
                float* ca = c + (jp * 2) * 4;
                float* cb = c + (jp * 2 + 1) * 4;
                mma_bf16(ca, ah, bh4[0], bh4[1]);
                mma_bf16(ca, al, bh4[0], bh4[1]);
                mma_bf16(ca, ah, bl4[0], bl4[1]);
                mma_bf16(cb, ah, bh4[2], bh4[3]);
                mma_bf16(cb, al, bh4[2], bh4[3]);
                mma_bf16(cb, ah, bl4[2], bl4[3]);
            }
        }

        // ---- Epilogue in fragments: relu(+bh), row LN, masked accumulate ----
        float m0v = sMask[r0], m1v = sMask[r1];
        float sum0 = 0.f, ss0 = 0.f, sum1 = 0.f, ss1 = 0.f;
#pragma unroll
        for (int jt = 0; jt < 16; jt++) {
            int col = jt * 8 + (lane & 3) * 2;
            float bh0 = sBh[col], bh1 = sBh[col + 1];
            float e0 = fmaxf(c[jt * 4 + 0] + bh0, 0.f);
            float e1 = fmaxf(c[jt * 4 + 1] + bh1, 0.f);
            float e2 = fmaxf(c[jt * 4 + 2] + bh0, 0.f);
            float e3 = fmaxf(c[jt * 4 + 3] + bh1, 0.f);
            sum0 += e0 + e1; ss0 += e0 * e0 + e1 * e1;
            sum1 += e2 + e3; ss1 += e2 * e2 + e3 * e3;
        }
#pragma unroll
        for (int o = 1; o <= 2; o <<= 1) {
            sum0 += __shfl_xor_sync(0xffffffffu, sum0, o);
            ss0  += __shfl_xor_sync(0xffffffffu, ss0, o);
            sum1 += __shfl_xor_sync(0xffffffffu, sum1, o);
            ss1  += __shfl_xor_sync(0xffffffffu, ss1, o);
        }
        float mean0 = sum0 * (1.f / 128.f);
        float rs0 = rsqrtf(ss0 * (1.f / 128.f) - mean0 * mean0 + 1e-5f) * m0v;
        float mean1 = sum1 * (1.f / 128.f);
        float rs1 = rsqrtf(ss1 * (1.f / 128.f) - mean1 * mean1 + 1e-5f) * m1v;
#pragma unroll
        for (int jt = 0; jt < 16; jt++) {
            int col = jt * 8 + (lane & 3) * 2;
            float bh0 = sBh[col], bh1 = sBh[col + 1];
            float e0 = fmaxf(c[jt * 4 + 0] + bh0, 0.f);
            float e1 = fmaxf(c[jt * 4 + 1] + bh1, 0.f);
            float e2 = fmaxf(c[jt * 4 + 2] + bh0, 0.f);
            float e3 = fmaxf(c[jt * 4 + 3] + bh1, 0.f);
            accS[jt * 4 + 0] += (e0 - mean0) * rs0;
            accS[jt * 4 + 1] += (e1 - mean0) * rs0;
            accS[jt * 4 + 2] += (e2 - mean1) * rs1;
            accS[jt * 4 + 3] += (e3 - mean1) * rs1;
        }
        cnt0 += m0v; cnt1 += m1v;
    }

    // Write partials directly from fragments
    unsigned pbase = OFF_PART + (unsigned)(chunk * 32 + b) * 16384u;
#pragma unroll
    for (int jt = 0; jt < 16; jt++) {
        int col = jt * 8 + (lane & 3) * 2;
        *(float2*)(g_scratch + pbase + (unsigned)r0 * 128u + col) = make_float2(accS[jt * 4 + 0], accS[jt * 4 + 1]);
        *(float2*)(g_scratch + pbase + (unsigned)r1 * 128u + col) = make_float2(accS[jt * 4 + 2], accS[jt * 4 + 3]);
    }
    if ((lane & 3) == 0) {
        unsigned cbase = OFF_CNT + (unsigned)(chunk * 32 + b) * 128u;
        g_scratch[cbase + r0] = cnt0;
        g_scratch[cbase + r1] = cnt1;
    }
}

// ---------------------------------------------------------------------------
// Kernel 2b: combine partials + outer-LN affine -> x0
// ---------------------------------------------------------------------------
__global__ void k_combine(const float* __restrict__ gh, const float* __restrict__ beh) {
    int bt = blockIdx.x;
    int j = threadIdx.x;
    float v = 0.f, c = 0.f;
#pragma unroll
    for (int q = 0; q < 4; q++) {
        v += g_scratch[OFF_PART + (unsigned)q * 524288u + (unsigned)bt * 128u + j];
        c += g_scratch[OFF_CNT + (unsigned)q * 4096u + bt];
    }
    g_scratch[OFF_X0 + (unsigned)bt * 128u + j] = gh[j] * v + beh[j] * c;
}

// ---------------------------------------------------------------------------
// Kernel 3: fused q/k/v/skip projections. 8 rows per block, 256 cols = threads.
// ---------------------------------------------------------------------------
template <int HIN>
__global__ void k_proj(unsigned xoff,
                       const float* __restrict__ Wq, const float* __restrict__ bq,
                       const float* __restrict__ Wk, const float* __restrict__ bk,
                       const float* __restrict__ Wv, const float* __restrict__ bv,
                       const float* __restrict__ Ws, const float* __restrict__ bs) {
    __shared__ float sX[8][HIN];
    const float* x = g_scratch + xoff;
    int r0 = blockIdx.x * 8;
    int tid = threadIdx.x;
    for (int idx = tid; idx < 8 * HIN; idx += 256) {
        int r = idx / HIN, i = idx % HIN;
        sX[r][i] = x[(r0 + r) * HIN + i];
    }
    __syncthreads();
    int j = tid;
    float aq[8], ak[8], av[8], as_[8];
    float bqv = bq[j], bkv = bk[j], bvv = bv[j], bsv = bs[j];
#pragma unroll
    for (int r = 0; r < 8; r++) { aq[r] = bqv; ak[r] = bkv; av[r] = bvv; as_[r] = bsv; }
    for (int i = 0; i < HIN; i++) {
        float wq = Wq[i * HD + j], wk = Wk[i * HD + j];
        float wv = Wv[i * HD + j], ws = Ws[i * HD + j];
#pragma unroll
        for (int r = 0; r < 8; r++) {
            float xv = sX[r][i];
            aq[r] += xv * wq; ak[r] += xv * wk;
            av[r] += xv * wv; as_[r] += xv * ws;
        }
    }
#pragma unroll
    for (int r = 0; r < 8; r++) {
        unsigned o = (unsigned)(r0 + r) * HD + j;
        g_scratch[OFF_Q + o] = aq[r];
        g_scratch[OFF_K + o] = ak[r];
        g_scratch[OFF_V + o] = av[r];
        g_scratch[OFF_S + o] = as_[r];
    }
}

// ---------------------------------------------------------------------------
// Kernel 4: attention. Block = (b, h, tile of 8 t's). 128 threads.
// ---------------------------------------------------------------------------
#define TB 8
__global__ void k_attn(const float* __restrict__ adj, const float* __restrict__ we,
                       unsigned outoff) {
    __shared__ float sK[128][65];
    __shared__ float sQ[TB][64];
    __shared__ float sW[TB][128];
    __shared__ float sB[TB];
    __shared__ float sQE[TB];
    __shared__ float redA[4], redB[4], redC[4];
    __shared__ float sPart[TB][64];

    int b = blockIdx.z, h = blockIdx.y, t0 = blockIdx.x * TB;
    int tid = threadIdx.x;
    const float* q = g_scratch + OFF_Q;
    const float* k = g_scratch + OFF_K;
    const float* v = g_scratch + OFF_V;
    const float* skip = g_scratch + OFF_S;
    float* xout = g_scratch + outoff;

    for (int idx = tid; idx < 128 * 64; idx += 128) {
        int s = idx >> 6, d = idx & 63;
        sK[s][d] = k[((b * NN + s) * NHEADS + h) * DH + d];
    }
    for (int idx = tid; idx < TB * 64; idx += 128) {
        int u = idx >> 6, d = idx & 63;
        sQ[u][d] = q[((b * NN + t0 + u) * NHEADS + h) * DH + d];
    }
    __syncthreads();

    {
        int u = tid >> 4, l = tid & 15;
        float p = 0.f;
#pragma unroll
        for (int c = 0; c < 4; c++) { int d = l + 16 * c; p += sQ[u][d] * we[h * DH + d]; }
        unsigned gm = 0xFFFFu << (tid & 16);
#pragma unroll
        for (int o = 8; o >= 1; o >>= 1) p += __shfl_xor_sync(gm, p, o);
        if (l == 0) sQE[u] = p;
    }
    __syncthreads();

    const float scale = 0.125f;
    int s = tid, lane = tid & 31, wid = tid >> 5;
    for (int u = 0; u < TB; u++) {
        int t = t0 + u;
        float a = adj[(b * NN + s) * NN + t];
        bool m = (a > 0.f) && (a < 1.0f);
        float av_ = m ? a : 0.f;
        float dot = 0.f;
#pragma unroll
        for (int d = 0; d < 64; d++) dot += sK[s][d] * sQ[u][d];
        float logit = m ? (dot + av_ * sQE[u]) * scale : -1e30f;
        float mx = logit;
#pragma unroll
        for (int o = 16; o >= 1; o >>= 1) mx = fmaxf(mx, __shfl_xor_sync(0xffffffffu, mx, o));
        if (lane == 0) redA[wid] = mx;
        __syncthreads();
        mx = fmaxf(fmaxf(redA[0], redA[1]), fmaxf(redA[2], redA[3]));
        float w = m ? __expf(logit - mx) : 0.f;
        float wa = w * av_;
        float sw = w, swa = wa;
#pragma unroll
        for (int o = 16; o >= 1; o >>= 1) {
            sw  += __shfl_xor_sync(0xffffffffu, sw, o);
            swa += __shfl_xor_sync(0xffffffffu, swa, o);
        }
        if (lane == 0) { redB[wid] = sw; redC[wid] = swa; }
        __syncthreads();
        float den = redB[0] + redB[1] + redB[2] + redB[3];
        float SWA = redC[0] + redC[1] + redC[2] + redC[3];
        float inv = 1.f / fmaxf(den, 1e-16f);
        sW[u][s] = w * inv;
        if (tid == 0) sB[u] = SWA * inv;
        __syncthreads();
    }

    int d = tid & 63, half = tid >> 6;
    float o8[TB];
#pragma unroll
    for (int u = 0; u < TB; u++) o8[u] = 0.f;
    for (int s2 = half * 64; s2 < half * 64 + 64; s2++) {
        float vv = v[((b * NN + s2) * NHEADS + h) * DH + d];
#pragma unroll
        for (int u = 0; u < TB; u++) o8[u] += sW[u][s2] * vv;
    }
    if (half == 1) {
#pragma unroll
        for (int u = 0; u < TB; u++) sPart[u][d] = o8[u];
    }
    __syncthreads();
    if (half == 0) {
        float wev = we[h * DH + d];
#pragma unroll
        for (int u = 0; u < TB; u++) {
            int t = t0 + u;
            unsigned idx = (unsigned)(b * NN + t) * HD + h * DH + d;
            float res = o8[u] + sPart[u][d] + sB[u] * wev + skip[idx];
            xout[idx] = fmaxf(res, 0.f);
        }
    }
}

// ---------------------------------------------------------------------------
// Kernel 5: gather agent rows
// ---------------------------------------------------------------------------
__global__ void k_gather(const int* __restrict__ agent, float* __restrict__ out) {
    int b = blockIdx.x, j = threadIdx.x;
    out[b * HD + j] = g_scratch[OFF_X2 + (unsigned)(b * NN + agent[b]) * HD + j];
}

// ---------------------------------------------------------------------------
extern "C" void kernel_launch(void* const* d_in, const int* in_sizes, int n_in,
                              void* d_out, int out_size) {
    const float* node_feat = (const float*)d_in[0];
    const int*   entity_type = (const int*)d_in[1];
    const float* adj = (const float*)d_in[2];
    const int*   agent_id = (const int*)d_in[3];
    const float* emb = (const float*)d_in[4];
    const float* W1 = (const float*)d_in[5];
    const float* b1 = (const float*)d_in[6];
    const float* g1 = (const float*)d_in[7];
    const float* be1 = (const float*)d_in[8];
    const float* Wh = (const float*)d_in[9];
    const float* bh = (const float*)d_in[10];
    const float* gh = (const float*)d_in[11];
    const float* beh = (const float*)d_in[12];
    const float* Wq1 = (const float*)d_in[13];
    const float* bq1 = (const float*)d_in[14];
    const float* Wk1 = (const float*)d_in[15];
    const float* bk1 = (const float*)d_in[16];
    const float* Wv1 = (const float*)d_in[17];
    const float* bv1 = (const float*)d_in[18];
    const float* We1 = (const float*)d_in[19];
    const float* Ws1 = (const float*)d_in[20];
    const float* bs1 = (const float*)d_in[21];
    const float* Wq2 = (const float*)d_in[22];
    const float* bq2 = (const float*)d_in[23];
    const float* Wk2 = (const float*)d_in[24];
    const float* bk2 = (const float*)d_in[25];
    const float* Wv2 = (const float*)d_in[26];
    const float* bv2 = (const float*)d_in[27];
    const float* We2 = (const float*)d_in[28];
    const float* Ws2 = (const float*)d_in[29];
    const float* bs2 = (const float*)d_in[30];

    cudaFuncSetAttribute(k_embed_mma, cudaFuncAttributeMaxDynamicSharedMemorySize, EMB_SMEM);

    k_base<<<BB * NN, 128>>>(node_feat, entity_type, emb, W1, b1);
    k_embed_mma<<<dim3(4, BB), 256, EMB_SMEM>>>(adj, W1, g1, be1, Wh, bh);
    k_combine<<<BB * NN, 128>>>(gh, beh);

    k_proj<128><<<(BB * NN) / 8, 256>>>(OFF_X0, Wq1, bq1, Wk1, bk1, Wv1, bv1, Ws1, bs1);
    k_attn<<<dim3(NN / TB, NHEADS, BB), 128>>>(adj, We1, OFF_X1);

    k_proj<256><<<(BB * NN) / 8, 256>>>(OFF_X1, Wq2, bq2, Wk2, bk2, Wv2, bv2, Ws2, bs2);
    k_attn<<<dim3(NN / TB, NHEADS, BB), 128>>>(adj, We2, OFF_X2);

    k_gather<<<BB, 256>>>(agent_id, (float*)d_out);
}

// round 4
// speedup vs baseline: 3.2924x; 1.8683x over previous
#include <cuda_runtime.h>
#include <cuda_bf16.h>
#include <cstdint>

// Problem constants
#define BB 32
#define NN 128
#define HH 128
#define HD 256
#define NHEADS 4
#define DH 64

// Scratch layout (floats)
#define OFF_BASE 0u
#define OFF_X0   524288u
#define OFF_Q    1048576u
#define OFF_K    2097152u
#define OFF_V    3145728u
#define OFF_S    4194304u
#define OFF_X1   5242880u
#define OFF_X2   6291456u
#define OFF_PART 7340032u   // 4 * 32 * 128 * 128 floats
#define OFF_CNT  9437184u   // 4 * 32 * 128 floats
#define SCRATCH_TOTAL 9453568u

__device__ float g_scratch[SCRATCH_TOTAL];

// ---------------------------------------------------------------------------
// PTX helpers (generic sm_80+ instructions only)
// ---------------------------------------------------------------------------
__device__ __forceinline__ uint32_t smem_u32(const void* p) {
    uint32_t a;
    asm("{ .reg .u64 t; cvta.to.shared.u64 t, %1; cvt.u32.u64 %0, t; }" : "=r"(a) : "l"(p));
    return a;
}
__device__ __forceinline__ void ldsm_x4(uint32_t& r0, uint32_t& r1, uint32_t& r2, uint32_t& r3, uint32_t addr) {
    asm volatile("ldmatrix.sync.aligned.m8n8.x4.shared.b16 {%0,%1,%2,%3}, [%4];"
                 : "=r"(r0), "=r"(r1), "=r"(r2), "=r"(r3) : "r"(addr));
}
__device__ __forceinline__ void mma_bf16(float* c, const uint32_t* a, uint32_t b0, uint32_t b1) {
    asm volatile("mma.sync.aligned.m16n8k16.row.col.f32.bf16.bf16.f32 "
                 "{%0,%1,%2,%3}, {%4,%5,%6,%7}, {%8,%9}, {%0,%1,%2,%3};"
                 : "+f"(c[0]), "+f"(c[1]), "+f"(c[2]), "+f"(c[3])
                 : "r"(a[0]), "r"(a[1]), "r"(a[2]), "r"(a[3]), "r"(b0), "r"(b1));
}
__device__ __forceinline__ void bf16_split(float v, uint32_t& hi_lane, uint32_t& lo_lane) {
    // helper unused (kept simple inline at call sites)
}

// ---------------------------------------------------------------------------
// Kernel 1: base[b,s,j] = node/emb part of msg @ W1 + b1
// ---------------------------------------------------------------------------
__global__ void k_base(const float* __restrict__ nf, const int* __restrict__ et,
                       const float* __restrict__ emb, const float* __restrict__ W1,
                       const float* __restrict__ b1) {
    int bn = blockIdx.x;
    int j  = threadIdx.x;
    const float* f = nf + bn * 9;
    const float* em = emb + et[bn] * 8;
    float acc = b1[j];
#pragma unroll
    for (int i = 0; i < 9; i++) acc += f[i] * W1[i * HH + j];
#pragma unroll
    for (int i = 0; i < 8; i++) acc += em[i] * W1[(9 + i) * HH + j];
    g_scratch[OFF_BASE + bn * HH + j] = acc;
}

// ---------------------------------------------------------------------------
// Kernel 2 (HMMA embed) — unchanged from Round 3 (proven)
// ---------------------------------------------------------------------------
#define PK 136
#define SM_BASE 0
#define SM_W17  512
#define SM_G1   1024
#define SM_BE1  1536
#define SM_BH   2048
#define SM_MASK 2560
#define SM_AHI  4096
#define SM_ALO  (SM_AHI + 128 * PK * 2)
#define SM_BHI  (SM_ALO + 128 * PK * 2)
#define SM_BLO  (SM_BHI + 128 * PK * 2)
#define EMB_SMEM (SM_BLO + 128 * PK * 2)

__global__ void __launch_bounds__(256, 1)
k_embed_mma(const float* __restrict__ adj, const float* __restrict__ W1,
            const float* __restrict__ g1, const float* __restrict__ be1,
            const float* __restrict__ Wh, const float* __restrict__ bh) {
    extern __shared__ char sm[];
    uint32_t smb = smem_u32(sm);
    float* sBase = (float*)(sm + SM_BASE);
    float* sW17  = (float*)(sm + SM_W17);
    float* sG1   = (float*)(sm + SM_G1);
    float* sBe1  = (float*)(sm + SM_BE1);
    float* sBh   = (float*)(sm + SM_BH);
    float* sMask = (float*)(sm + SM_MASK);

    int tid = threadIdx.x;
    int lane = tid & 31, wid = tid >> 5;
    int chunk = blockIdx.x, b = blockIdx.y;

    if (tid < 128) {
        sW17[tid] = W1[17 * HH + tid];
        sG1[tid]  = g1[tid];
        sBe1[tid] = be1[tid];
        sBh[tid]  = bh[tid];
    }

    for (int idx = tid; idx < 16384; idx += 256) {
        int k = idx >> 7, j = idx & 127;
        float w = Wh[idx];
        __nv_bfloat16 h = __float2bfloat16(w);
        __nv_bfloat16 l = __float2bfloat16(w - __bfloat162float(h));
        *(__nv_bfloat16*)(sm + SM_BHI + (j * PK + k) * 2) = h;
        *(__nv_bfloat16*)(sm + SM_BLO + (j * PK + k) * 2) = l;
    }

    int tA = tid >> 1, half = tid & 1;
    int m0 = wid * 16;
    int r0 = m0 + (lane >> 2), r1 = r0 + 8;

    float accS[64];
#pragma unroll
    for (int u = 0; u < 64; u++) accS[u] = 0.f;
    float cnt0 = 0.f, cnt1 = 0.f;

    int s0 = chunk * 32;
    for (int si = 0; si < 32; si++) {
        int s = s0 + si;

        __syncthreads();
        if (tid < 128) sBase[tid] = g_scratch[OFF_BASE + (b * NN + s) * HH + tid];
        {
            float araw = adj[(b * NN + s) * NN + tA];
            bool mk = (araw > 0.f) && (araw < 1.0f);
            if (half == 0) sMask[tA] = mk ? 1.f : 0.f;
        }
        __syncthreads();

        {
            float araw = adj[(b * NN + s) * NN + tA];
            bool mk = (araw > 0.f) && (araw < 1.0f);
            float at = mk ? araw : 0.f;
            int c0 = half * 64;
            float sum = 0.f, ssum = 0.f;
#pragma unroll 4
            for (int j = 0; j < 64; j++) {
                float y = fmaxf(sBase[c0 + j] + at * sW17[c0 + j], 0.f);
                sum += y; ssum += y * y;
            }
            sum  += __shfl_xor_sync(0xffffffffu, sum, 1);
            ssum += __shfl_xor_sync(0xffffffffu, ssum, 1);
            float mean = sum * (1.f / 128.f);
            float rs = rsqrtf(ssum * (1.f / 128.f) - mean * mean + 1e-5f);
#pragma unroll 2
            for (int j2 = 0; j2 < 32; j2++) {
                int j = c0 + j2 * 2;
                float y0 = fmaxf(sBase[j] + at * sW17[j], 0.f);
                float y1 = fmaxf(sBase[j + 1] + at * sW17[j + 1], 0.f);
                float h0 = (y0 - mean) * rs * sG1[j] + sBe1[j];
                float h1 = (y1 - mean) * rs * sG1[j + 1] + sBe1[j + 1];
                __nv_bfloat16 a0 = __float2bfloat16(h0), a1 = __float2bfloat16(h1);
                __nv_bfloat16 b0 = __float2bfloat16(h0 - __bfloat162float(a0));
                __nv_bfloat16 b1 = __float2bfloat16(h1 - __bfloat162float(a1));
                uint32_t hiw = (uint32_t)__bfloat16_as_ushort(a0) | ((uint32_t)__bfloat16_as_ushort(a1) << 16);
                uint32_t low = (uint32_t)__bfloat16_as_ushort(b0) | ((uint32_t)__bfloat16_as_ushort(b1) << 16);
                uint32_t off = (uint32_t)(tA * PK + j) * 2;
                *(uint32_t*)(sm + SM_AHI + off) = hiw;
                *(uint32_t*)(sm + SM_ALO + off) = low;
            }
        }
        __syncthreads();

        float c[64];
#pragma unroll
        for (int u = 0; u < 64; u++) c[u] = 0.f;

        uint32_t aoff = (uint32_t)((m0 + (lane & 15)) * PK + (lane >> 4) * 8) * 2;
        uint32_t brow = (uint32_t)(((lane & 16) >> 1) + (lane & 7));
        uint32_t bk   = (uint32_t)(((lane >> 3) & 1) * 8);

#pragma unroll
        for (int kk = 0; kk < 8; kk++) {
            uint32_t ah[4], al[4];
            uint32_t ka = aoff + (uint32_t)(kk * 16) * 2;
            ldsm_x4(ah[0], ah[1], ah[2], ah[3], smb + SM_AHI + ka);
            ldsm_x4(al[0], al[1], al[2], al[3], smb + SM_ALO + ka);
#pragma unroll
            for (int jp = 0; jp < 8; jp++) {
                uint32_t boff = (uint32_t)((jp * 16 + brow) * PK + kk * 16 + bk) * 2;
                uint32_t bh4[4], bl4[4];
                ldsm_x4(bh4[0], bh4[1], bh4[2], bh4[3], smb + SM_BHI + boff);
                ldsm_x4(bl4[0], bl4[1], bl4[2], bl4[3], smb + SM_BLO + boff);
                float* ca = c + (jp * 2) * 4;
                float* cb = c + (jp * 2 + 1) * 4;
                mma_bf16(ca, ah, bh4[0], bh4[1]);
                mma_bf16(ca, al, bh4[0], bh4[1]);
                mma_bf16(ca, ah, bl4[0], bl4[1]);
                mma_bf16(cb, ah, bh4[2], bh4[3]);
                mma_bf16(cb, al, bh4[2], bh4[3]);
                mma_bf16(cb, ah, bl4[2], bl4[3]);
            }
        }

        float m0v = sMask[r0], m1v = sMask[r1];
        float sum0 = 0.f, ss0 = 0.f, sum1 = 0.f, ss1 = 0.f;
#pragma unroll
        for (int jt = 0; jt < 16; jt++) {
            int col = jt * 8 + (lane & 3) * 2;
            float bh0 = sBh[col], bh1 = sBh[col + 1];
            float e0 = fmaxf(c[jt * 4 + 0] + bh0, 0.f);
            float e1 = fmaxf(c[jt * 4 + 1] + bh1, 0.f);
            float e2 = fmaxf(c[jt * 4 + 2] + bh0, 0.f);
            float e3 = fmaxf(c[jt * 4 + 3] + bh1, 0.f);
            sum0 += e0 + e1; ss0 += e0 * e0 + e1 * e1;
            sum1 += e2 + e3; ss1 += e2 * e2 + e3 * e3;
        }
#pragma unroll
        for (int o = 1; o <= 2; o <<= 1) {
            sum0 += __shfl_xor_sync(0xffffffffu, sum0, o);
            ss0  += __shfl_xor_sync(0xffffffffu, ss0, o);
            sum1 += __shfl_xor_sync(0xffffffffu, sum1, o);
            ss1  += __shfl_xor_sync(0xffffffffu, ss1, o);
        }
        float mean0 = sum0 * (1.f / 128.f);
        float rs0 = rsqrtf(ss0 * (1.f / 128.f) - mean0 * mean0 + 1e-5f) * m0v;
        float mean1 = sum1 * (1.f / 128.f);
        float rs1 = rsqrtf(ss1 * (1.f / 128.f) - mean1 * mean1 + 1e-5f) * m1v;
#pragma unroll
        for (int jt = 0; jt < 16; jt++) {
            int col = jt * 8 + (lane & 3) * 2;
            float bh0 = sBh[col], bh1 = sBh[col + 1];
            float e0 = fmaxf(c[jt * 4 + 0] + bh0, 0.f);
            float e1 = fmaxf(c[jt * 4 + 1] + bh1, 0.f);
            float e2 = fmaxf(c[jt * 4 + 2] + bh0, 0.f);
            float e3 = fmaxf(c[jt * 4 + 3] + bh1, 0.f);
            accS[jt * 4 + 0] += (e0 - mean0) * rs0;
            accS[jt * 4 + 1] += (e1 - mean0) * rs0;
            accS[jt * 4 + 2] += (e2 - mean1) * rs1;
            accS[jt * 4 + 3] += (e3 - mean1) * rs1;
        }
        cnt0 += m0v; cnt1 += m1v;
    }

    unsigned pbase = OFF_PART + (unsigned)(chunk * 32 + b) * 16384u;
#pragma unroll
    for (int jt = 0; jt < 16; jt++) {
        int col = jt * 8 + (lane & 3) * 2;
        *(float2*)(g_scratch + pbase + (unsigned)r0 * 128u + col) = make_float2(accS[jt * 4 + 0], accS[jt * 4 + 1]);
        *(float2*)(g_scratch + pbase + (unsigned)r1 * 128u + col) = make_float2(accS[jt * 4 + 2], accS[jt * 4 + 3]);
    }
    if ((lane & 3) == 0) {
        unsigned cbase = OFF_CNT + (unsigned)(chunk * 32 + b) * 128u;
        g_scratch[cbase + r0] = cnt0;
        g_scratch[cbase + r1] = cnt1;
    }
}

// ---------------------------------------------------------------------------
// Kernel 2b: combine partials + outer-LN affine -> x0
// ---------------------------------------------------------------------------
__global__ void k_combine(const float* __restrict__ gh, const float* __restrict__ beh) {
    int bt = blockIdx.x;
    int j = threadIdx.x;
    float v = 0.f, c = 0.f;
#pragma unroll
    for (int q = 0; q < 4; q++) {
        v += g_scratch[OFF_PART + (unsigned)q * 524288u + (unsigned)bt * 128u + j];
        c += g_scratch[OFF_CNT + (unsigned)q * 4096u + bt];
    }
    g_scratch[OFF_X0 + (unsigned)bt * 128u + j] = gh[j] * v + beh[j] * c;
}

// ---------------------------------------------------------------------------
// Kernel 3 (HMMA proj): block tile 64 rows x 256 cols (blockIdx.y selects the
// matrix: 0=Q 1=K 2=V 3=S). K staged in 64-wide chunks. 3-term bf16 split.
// ---------------------------------------------------------------------------
template <int HIN>
__global__ void __launch_bounds__(256, 1)
k_proj_mma(unsigned xoff,
           const float* __restrict__ Wq, const float* __restrict__ bq,
           const float* __restrict__ Wk, const float* __restrict__ bk,
           const float* __restrict__ Wv, const float* __restrict__ bv,
           const float* __restrict__ Ws, const float* __restrict__ bs) {
    extern __shared__ char sm[];
    constexpr int PJ = HIN + 8;
    constexpr int PW = 72;
    constexpr int XHI = 0;
    constexpr int XLO = XHI + 64 * PJ * 2;
    constexpr int WHI = XLO + 64 * PJ * 2;
    constexpr int WLO = WHI + 256 * PW * 2;
    constexpr int RSH = (HIN == 128) ? 7 : 8;

    uint32_t smb = smem_u32(sm);
    int tid = threadIdx.x, lane = tid & 31, wid = tid >> 5;
    int r0 = blockIdx.x * 64;
    int my = blockIdx.y;
    const float* W    = (my == 0) ? Wq : (my == 1) ? Wk : (my == 2) ? Wv : Ws;
    const float* bias = (my == 0) ? bq : (my == 1) ? bk : (my == 2) ? bv : bs;
    unsigned outoff   = (my == 0) ? OFF_Q : (my == 1) ? OFF_K : (my == 2) ? OFF_V : OFF_S;
    const float* x = g_scratch + xoff;

    // Load X tile [64 x HIN] hi/lo
    for (int idx = tid; idx < 64 * HIN; idx += 256) {
        int r = idx >> RSH, k = idx & (HIN - 1);
        float v = x[(unsigned)(r0 + r) * HIN + k];
        __nv_bfloat16 h = __float2bfloat16(v);
        __nv_bfloat16 l = __float2bfloat16(v - __bfloat162float(h));
        *(__nv_bfloat16*)(sm + XHI + (r * PJ + k) * 2) = h;
        *(__nv_bfloat16*)(sm + XLO + (r * PJ + k) * 2) = l;
    }

    int mrow = wid & 3, ncol = wid >> 2;
    int m0 = mrow * 16;
    uint32_t aoff = (uint32_t)((m0 + (lane & 15)) * PJ + (lane >> 4) * 8) * 2;
    uint32_t brow = (uint32_t)(((lane & 16) >> 1) + (lane & 7));
    uint32_t bk_  = (uint32_t)(((lane >> 3) & 1) * 8);

    float c[64];
#pragma unroll
    for (int u = 0; u < 64; u++) c[u] = 0.f;

    for (int kc = 0; kc < HIN / 64; kc++) {
        __syncthreads();
        // stage W chunk [64 k x 256 n] as [n][k] hi/lo
        for (int idx = tid; idx < 64 * 256; idx += 256) {
            int k = idx >> 8, n = idx & 255;
            float w = W[(unsigned)(kc * 64 + k) * HD + n];
            __nv_bfloat16 h = __float2bfloat16(w);
            __nv_bfloat16 l = __float2bfloat16(w - __bfloat162float(h));
            *(__nv_bfloat16*)(sm + WHI + (n * PW + k) * 2) = h;
            *(__nv_bfloat16*)(sm + WLO + (n * PW + k) * 2) = l;
        }
        __syncthreads();

#pragma unroll
        for (int k2 = 0; k2 < 4; k2++) {
            int kk = kc * 4 + k2;
            uint32_t ah[4], al[4];
            uint32_t ka = aoff + (uint32_t)(kk * 16) * 2;
            ldsm_x4(ah[0], ah[1], ah[2], ah[3], smb + XHI + ka);
            ldsm_x4(al[0], al[1], al[2], al[3], smb + XLO + ka);
#pragma unroll
            for (int jp = 0; jp < 8; jp++) {
                uint32_t boff = (uint32_t)((ncol * 128 + jp * 16 + brow) * PW + k2 * 16 + bk_) * 2;
                uint32_t bh4[4], bl4[4];
                ldsm_x4(bh4[0], bh4[1], bh4[2], bh4[3], smb + WHI + boff);
                ldsm_x4(bl4[0], bl4[1], bl4[2], bl4[3], smb + WLO + boff);
                float* ca = c + (jp * 2) * 4;
                float* cb = c + (jp * 2 + 1) * 4;
                mma_bf16(ca, ah, bh4[0], bh4[1]);
                mma_bf16(ca, al, bh4[0], bh4[1]);
                mma_bf16(ca, ah, bl4[0], bl4[1]);
                mma_bf16(cb, ah, bh4[2], bh4[3]);
                mma_bf16(cb, al, bh4[2], bh4[3]);
                mma_bf16(cb, ah, bl4[2], bl4[3]);
            }
        }
    }

    // Epilogue: + bias, store
    int rA = r0 + m0 + (lane >> 2);
    int rB = rA + 8;
#pragma unroll
    for (int jt = 0; jt < 16; jt++) {
        int col = ncol * 128 + jt * 8 + (lane & 3) * 2;
        float b0 = bias[col], b1 = bias[col + 1];
        *(float2*)(g_scratch + outoff + (unsigned)rA * HD + col) =
            make_float2(c[jt * 4 + 0] + b0, c[jt * 4 + 1] + b1);
        *(float2*)(g_scratch + outoff + (unsigned)rB * HD + col) =
            make_float2(c[jt * 4 + 2] + b0, c[jt * 4 + 3] + b1);
    }
}

// ---------------------------------------------------------------------------
// Kernel 4: attention (restructured: batched reductions, 4 barriers total)
// ---------------------------------------------------------------------------
#define TB 8
__global__ void __launch_bounds__(128)
k_attn(const float* __restrict__ adj, const float* __restrict__ we, unsigned outoff) {
    __shared__ float sK[128][65];
    __shared__ float sQ[TB][64];
    __shared__ float sW[TB][128];
    __shared__ float sB[TB];
    __shared__ float sQE[TB];
    __shared__ float redM[4][TB], redS[4][TB], redWA[4][TB];
    __shared__ float sPart[TB][64];

    int b = blockIdx.z, h = blockIdx.y, t0 = blockIdx.x * TB;
    int tid = threadIdx.x, lane = tid & 31, wid = tid >> 5;
    const float* q = g_scratch + OFF_Q;
    const float* k = g_scratch + OFF_K;
    const float* v = g_scratch + OFF_V;
    const float* skip = g_scratch + OFF_S;
    float* xout = g_scratch + outoff;

    for (int idx = tid; idx < 128 * 64; idx += 128) {
        int s = idx >> 6, d = idx & 63;
        sK[s][d] = k[((b * NN + s) * NHEADS + h) * DH + d];
    }
    for (int idx = tid; idx < TB * 64; idx += 128) {
        int u = idx >> 6, d = idx & 63;
        sQ[u][d] = q[((b * NN + t0 + u) * NHEADS + h) * DH + d];
    }
    __syncthreads();

    { // qe[u] = q_t . we_h
        int u = tid >> 4, l = tid & 15;
        float p = 0.f;
#pragma unroll
        for (int c = 0; c < 4; c++) { int d = l + 16 * c; p += sQ[u][d] * we[h * DH + d]; }
        unsigned gm = 0xFFFFu << (tid & 16);
#pragma unroll
        for (int o = 8; o >= 1; o >>= 1) p += __shfl_xor_sync(gm, p, o);
        if (l == 0) sQE[u] = p;
    }
    __syncthreads();

    const float scale = 0.125f;
    int s = tid;

    // adj row segment for this s: 8 consecutive t's
    float4 a0 = *(const float4*)(adj + (unsigned)(b * NN + s) * NN + t0);
    float4 a1 = *(const float4*)(adj + (unsigned)(b * NN + s) * NN + t0 + 4);
    float av8[TB] = {a0.x, a0.y, a0.z, a0.w, a1.x, a1.y, a1.z, a1.w};
    float m8[TB], dot[TB];
#pragma unroll
    for (int u = 0; u < TB; u++) {
        bool m = (av8[u] > 0.f) && (av8[u] < 1.0f);
        m8[u] = m ? 1.f : 0.f;
        av8[u] = m ? av8[u] : 0.f;
        dot[u] = 0.f;
    }
#pragma unroll 8
    for (int d = 0; d < 64; d++) {
        float kv = sK[s][d];
#pragma unroll
        for (int u = 0; u < TB; u++) dot[u] += kv * sQ[u][d];
    }
    float lg[TB];
#pragma unroll
    for (int u = 0; u < TB; u++)
        lg[u] = (m8[u] > 0.f) ? (dot[u] + av8[u] * sQE[u]) * scale : -1e30f;

    // batched warp max
#pragma unroll
    for (int u = 0; u < TB; u++) {
        float mx = lg[u];
#pragma unroll
        for (int o = 16; o >= 1; o >>= 1) mx = fmaxf(mx, __shfl_xor_sync(0xffffffffu, mx, o));
        if (lane == 0) redM[wid][u] = mx;
    }
    __syncthreads();

    float w8[TB], wa8[TB];
#pragma unroll
    for (int u = 0; u < TB; u++) {
        float mx = fmaxf(fmaxf(redM[0][u], redM[1][u]), fmaxf(redM[2][u], redM[3][u]));
        float w = (m8[u] > 0.f) ? __expf(lg[u] - mx) : 0.f;
        w8[u] = w; wa8[u] = w * av8[u];
    }
#pragma unroll
    for (int u = 0; u < TB; u++) {
        float sw = w8[u], swa = wa8[u];
#pragma unroll
        for (int o = 16; o >= 1; o >>= 1) {
            sw  += __shfl_xor_sync(0xffffffffu, sw, o);
            swa += __shfl_xor_sync(0xffffffffu, swa, o);
        }
        if (lane == 0) { redS[wid][u] = sw; redWA[wid][u] = swa; }
    }
    __syncthreads();

#pragma unroll
    for (int u = 0; u < TB; u++) {
        float den = redS[0][u] + redS[1][u] + redS[2][u] + redS[3][u];
        float SWA = redWA[0][u] + redWA[1][u] + redWA[2][u] + redWA[3][u];
        float inv = 1.f / fmaxf(den, 1e-16f);
        sW[u][s] = w8[u] * inv;
        if (tid == u) sB[u] = SWA * inv;
    }
    __syncthreads();

    // out[t,d] = sum_s alpha * v  (+ beta*we + skip, relu)
    int d = tid & 63, half = tid >> 6;
    float o8[TB];
#pragma unroll
    for (int u = 0; u < TB; u++) o8[u] = 0.f;
    for (int s2 = half * 64; s2 < half * 64 + 64; s2++) {
        float vv = v[((b * NN + s2) * NHEADS + h) * DH + d];
#pragma unroll
        for (int u = 0; u < TB; u++) o8[u] += sW[u][s2] * vv;
    }
    if (half == 1) {
#pragma unroll
        for (int u = 0; u < TB; u++) sPart[u][d] = o8[u];
    }
    __syncthreads();
    if (half == 0) {
        float wev = we[h * DH + d];
#pragma unroll
        for (int u = 0; u < TB; u++) {
            int t = t0 + u;
            unsigned idx = (unsigned)(b * NN + t) * HD + h * DH + d;
            float res = o8[u] + sPart[u][d] + sB[u] * wev + skip[idx];
            xout[idx] = fmaxf(res, 0.f);
        }
    }
}

// ---------------------------------------------------------------------------
// Kernel 5: gather agent rows
// ---------------------------------------------------------------------------
__global__ void k_gather(const int* __restrict__ agent, float* __restrict__ out) {
    int b = blockIdx.x, j = threadIdx.x;
    out[b * HD + j] = g_scratch[OFF_X2 + (unsigned)(b * NN + agent[b]) * HD + j];
}

// ---------------------------------------------------------------------------
extern "C" void kernel_launch(void* const* d_in, const int* in_sizes, int n_in,
                              void* d_out, int out_size) {
    const float* node_feat = (const float*)d_in[0];
    const int*   entity_type = (const int*)d_in[1];
    const float* adj = (const float*)d_in[2];
    const int*   agent_id = (const int*)d_in[3];
    const float* emb = (const float*)d_in[4];
    const float* W1 = (const float*)d_in[5];
    const float* b1 = (const float*)d_in[6];
    const float* g1 = (const float*)d_in[7];
    const float* be1 = (const float*)d_in[8];
    const float* Wh = (const float*)d_in[9];
    const float* bh = (const float*)d_in[10];
    const float* gh = (const float*)d_in[11];
    const float* beh = (const float*)d_in[12];
    const float* Wq1 = (const float*)d_in[13];
    const float* bq1 = (const float*)d_in[14];
    const float* Wk1 = (const float*)d_in[15];
    const float* bk1 = (const float*)d_in[16];
    const float* Wv1 = (const float*)d_in[17];
    const float* bv1 = (const float*)d_in[18];
    const float* We1 = (const float*)d_in[19];
    const float* Ws1 = (const float*)d_in[20];
    const float* bs1 = (const float*)d_in[21];
    const float* Wq2 = (const float*)d_in[22];
    const float* bq2 = (const float*)d_in[23];
    const float* Wk2 = (const float*)d_in[24];
    const float* bk2 = (const float*)d_in[25];
    const float* Wv2 = (const float*)d_in[26];
    const float* bv2 = (const float*)d_in[27];
    const float* We2 = (const float*)d_in[28];
    const float* Ws2 = (const float*)d_in[29];
    const float* bs2 = (const float*)d_in[30];

    constexpr int PROJ128_SMEM = 2 * 64 * 136 * 2 + 2 * 256 * 72 * 2; // 108544
    constexpr int PROJ256_SMEM = 2 * 64 * 264 * 2 + 2 * 256 * 72 * 2; // 141312

    cudaFuncSetAttribute(k_embed_mma, cudaFuncAttributeMaxDynamicSharedMemorySize, EMB_SMEM);
    cudaFuncSetAttribute(k_proj_mma<128>, cudaFuncAttributeMaxDynamicSharedMemorySize, PROJ128_SMEM);
    cudaFuncSetAttribute(k_proj_mma<256>, cudaFuncAttributeMaxDynamicSharedMemorySize, PROJ256_SMEM);

    k_base<<<BB * NN, 128>>>(node_feat, entity_type, emb, W1, b1);
    k_embed_mma<<<dim3(4, BB), 256, EMB_SMEM>>>(adj, W1, g1, be1, Wh, bh);
    k_combine<<<BB * NN, 128>>>(gh, beh);

    k_proj_mma<128><<<dim3(64, 4), 256, PROJ128_SMEM>>>(OFF_X0, Wq1, bq1, Wk1, bk1, Wv1, bv1, Ws1, bs1);
    k_attn<<<dim3(NN / TB, NHEADS, BB), 128>>>(adj, We1, OFF_X1);

    k_proj_mma<256><<<dim3(64, 4), 256, PROJ256_SMEM>>>(OFF_X1, Wq2, bq2, Wk2, bk2, Wv2, bv2, Ws2, bs2);
    k_attn<<<dim3(NN / TB, NHEADS, BB), 128>>>(adj, We2, OFF_X2);

    k_gather<<<BB, 256>>>(agent_id, (float*)d_out);
}

// round 5
// speedup vs baseline: 3.6485x; 1.1081x over previous
#include <cuda_runtime.h>
#include <cuda_bf16.h>
#include <cstdint>

// Problem constants
#define BB 32
#define NN 128
#define HH 128
#define HD 256
#define NHEADS 4
#define DH 64

// Scratch layout (floats)
#define OFF_BASE 0u
#define OFF_X0   524288u
#define OFF_Q    1048576u
#define OFF_K    2097152u
#define OFF_V    3145728u
#define OFF_S    4194304u
#define OFF_X1   5242880u
#define OFF_X2   6291456u
#define OFF_PART 7340032u   // 4 * 32 * 128 * 128 floats
#define OFF_CNT  9437184u   // 4 * 32 * 128 floats
#define OFF_WF   9453568u   // fragment-packed weight splits (393216 floats)
#define SCRATCH_TOTAL 9846784u

__device__ float g_scratch[SCRATCH_TOTAL];

// ---------------------------------------------------------------------------
// PTX helpers (generic sm_80+ instructions only)
// ---------------------------------------------------------------------------
__device__ __forceinline__ uint32_t smem_u32(const void* p) {
    uint32_t a;
    asm("{ .reg .u64 t; cvta.to.shared.u64 t, %1; cvt.u32.u64 %0, t; }" : "=r"(a) : "l"(p));
    return a;
}
__device__ __forceinline__ void ldsm_x4(uint32_t& r0, uint32_t& r1, uint32_t& r2, uint32_t& r3, uint32_t addr) {
    asm volatile("ldmatrix.sync.aligned.m8n8.x4.shared.b16 {%0,%1,%2,%3}, [%4];"
                 : "=r"(r0), "=r"(r1), "=r"(r2), "=r"(r3) : "r"(addr));
}
__device__ __forceinline__ void mma_bf16(float* c, const uint32_t* a, uint32_t b0, uint32_t b1) {
    asm volatile("mma.sync.aligned.m16n8k16.row.col.f32.bf16.bf16.f32 "
                 "{%0,%1,%2,%3}, {%4,%5,%6,%7}, {%8,%9}, {%0,%1,%2,%3};"
                 : "+f"(c[0]), "+f"(c[1]), "+f"(c[2]), "+f"(c[3])
                 : "r"(a[0]), "r"(a[1]), "r"(a[2]), "r"(a[3]), "r"(b0), "r"(b1));
}
__device__ __forceinline__ uint32_t pack_hi2(float a, float b) {
    return (uint32_t)__bfloat16_as_ushort(__float2bfloat16(a))
         | ((uint32_t)__bfloat16_as_ushort(__float2bfloat16(b)) << 16);
}
__device__ __forceinline__ uint32_t pack_lo2(float a, float b) {
    float ra = a - __bfloat162float(__float2bfloat16(a));
    float rb = b - __bfloat162float(__float2bfloat16(b));
    return (uint32_t)__bfloat16_as_ushort(__float2bfloat16(ra))
         | ((uint32_t)__bfloat16_as_ushort(__float2bfloat16(rb)) << 16);
}

// ---------------------------------------------------------------------------
// Kernel 0: pre-split proj weights into fragment-packed global layout.
// Per (matrix, ntile, ktile, lane): uint4 {b0hi, b1hi, b0lo, b1lo} matching
// the m16n8k16 B fragment each lane needs.
// Layer1 (K=128): 4 mats x 32 nt x 8 kt x 32 lanes;  Layer2 (K=256): x 16 kt.
// ---------------------------------------------------------------------------
__global__ void k_wsplit(const float* __restrict__ Wq1, const float* __restrict__ Wk1,
                         const float* __restrict__ Wv1, const float* __restrict__ Ws1,
                         const float* __restrict__ Wq2, const float* __restrict__ Wk2,
                         const float* __restrict__ Wv2, const float* __restrict__ Ws2) {
    unsigned idx = blockIdx.x * 256u + threadIdx.x;   // 0 .. 98303
    const float* W;
    unsigned base, rem;
    if (idx < 32768u) {
        int mat = idx >> 13; rem = idx & 8191u;
        W = (mat == 0) ? Wq1 : (mat == 1) ? Wk1 : (mat == 2) ? Wv1 : Ws1;
        base = OFF_WF + (unsigned)mat * 32768u;
    } else {
        unsigned j = idx - 32768u;
        int mat = j >> 14; rem = j & 16383u;
        W = (mat == 0) ? Wq2 : (mat == 1) ? Wk2 : (mat == 2) ? Wv2 : Ws2;
        base = OFF_WF + 131072u + (unsigned)mat * 65536u;
    }
    int KT = (idx < 32768u) ? 8 : 16;
    int lane = rem & 31;
    int tile = rem >> 5;           // nt*KT + kt
    int kt = tile % KT;
    int nt = tile / KT;
    int n = nt * 8 + (lane >> 2);
    int k0 = kt * 16 + (lane & 3) * 2;
    float w00 = W[(unsigned)k0 * HD + n],       w01 = W[(unsigned)(k0 + 1) * HD + n];
    float w10 = W[(unsigned)(k0 + 8) * HD + n], w11 = W[(unsigned)(k0 + 9) * HD + n];
    uint4 out;
    out.x = pack_hi2(w00, w01);
    out.y = pack_hi2(w10, w11);
    out.z = pack_lo2(w00, w01);
    out.w = pack_lo2(w10, w11);
    *(uint4*)(g_scratch + base + (unsigned)rem * 4u) = out;
}

// ---------------------------------------------------------------------------
// Kernel 1: base[b,s,j] = node/emb part of msg @ W1 + b1
// ---------------------------------------------------------------------------
__global__ void k_base(const float* __restrict__ nf, const int* __restrict__ et,
                       const float* __restrict__ emb, const float* __restrict__ W1,
                       const float* __restrict__ b1) {
    int bn = blockIdx.x;
    int j  = threadIdx.x;
    const float* f = nf + bn * 9;
    const float* em = emb + et[bn] * 8;
    float acc = b1[j];
#pragma unroll
    for (int i = 0; i < 9; i++) acc += f[i] * W1[i * HH + j];
#pragma unroll
    for (int i = 0; i < 8; i++) acc += em[i] * W1[(9 + i) * HH + j];
    g_scratch[OFF_BASE + bn * HH + j] = acc;
}

// ---------------------------------------------------------------------------
// Kernel 2 (HMMA embed) — unchanged (proven)
// ---------------------------------------------------------------------------
#define PK 136
#define SM_BASE 0
#define SM_W17  512
#define SM_G1   1024
#define SM_BE1  1536
#define SM_BH   2048
#define SM_MASK 2560
#define SM_AHI  4096
#define SM_ALO  (SM_AHI + 128 * PK * 2)
#define SM_BHI  (SM_ALO + 128 * PK * 2)
#define SM_BLO  (SM_BHI + 128 * PK * 2)
#define EMB_SMEM (SM_BLO + 128 * PK * 2)

__global__ void __launch_bounds__(256, 1)
k_embed_mma(const float* __restrict__ adj, const float* __restrict__ W1,
            const float* __restrict__ g1, const float* __restrict__ be1,
            const float* __restrict__ Wh, const float* __restrict__ bh) {
    extern __shared__ char sm[];
    uint32_t smb = smem_u32(sm);
    float* sBase = (float*)(sm + SM_BASE);
    float* sW17  = (float*)(sm + SM_W17);
    float* sG1   = (float*)(sm + SM_G1);
    float* sBe1  = (float*)(sm + SM_BE1);
    float* sBh   = (float*)(sm + SM_BH);
    float* sMask = (float*)(sm + SM_MASK);

    int tid = threadIdx.x;
    int lane = tid & 31, wid = tid >> 5;
    int chunk = blockIdx.x, b = blockIdx.y;

    if (tid < 128) {
        sW17[tid] = W1[17 * HH + tid];
        sG1[tid]  = g1[tid];
        sBe1[tid] = be1[tid];
        sBh[tid]  = bh[tid];
    }

    for (int idx = tid; idx < 16384; idx += 256) {
        int k = idx >> 7, j = idx & 127;
        float w = Wh[idx];
        __nv_bfloat16 h = __float2bfloat16(w);
        __nv_bfloat16 l = __float2bfloat16(w - __bfloat162float(h));
        *(__nv_bfloat16*)(sm + SM_BHI + (j * PK + k) * 2) = h;
        *(__nv_bfloat16*)(sm + SM_BLO + (j * PK + k) * 2) = l;
    }

    int tA = tid >> 1, half = tid & 1;
    int m0 = wid * 16;
    int r0 = m0 + (lane >> 2), r1 = r0 + 8;

    float accS[64];
#pragma unroll
    for (int u = 0; u < 64; u++) accS[u] = 0.f;
    float cnt0 = 0.f, cnt1 = 0.f;

    int s0 = chunk * 32;
    for (int si = 0; si < 32; si++) {
        int s = s0 + si;

        __syncthreads();
        if (tid < 128) sBase[tid] = g_scratch[OFF_BASE + (b * NN + s) * HH + tid];
        {
            float araw = adj[(b * NN + s) * NN + tA];
            bool mk = (araw > 0.f) && (araw < 1.0f);
            if (half == 0) sMask[tA] = mk ? 1.f : 0.f;
        }
        __syncthreads();

        {
            float araw = adj[(b * NN + s) * NN + tA];
            bool mk = (araw > 0.f) && (araw < 1.0f);
            float at = mk ? araw : 0.f;
            int c0 = half * 64;
            float sum = 0.f, ssum = 0.f;
#pragma unroll 4
            for (int j = 0; j < 64; j++) {
                float y = fmaxf(sBase[c0 + j] + at * sW17[c0 + j], 0.f);
                sum += y; ssum += y * y;
            }
            sum  += __shfl_xor_sync(0xffffffffu, sum, 1);
            ssum += __shfl_xor_sync(0xffffffffu, ssum, 1);
            float mean = sum * (1.f / 128.f);
            float rs = rsqrtf(ssum * (1.f / 128.f) - mean * mean + 1e-5f);
#pragma unroll 2
            for (int j2 = 0; j2 < 32; j2++) {
                int j = c0 + j2 * 2;
                float y0 = fmaxf(sBase[j] + at * sW17[j], 0.f);
                float y1 = fmaxf(sBase[j + 1] + at * sW17[j + 1], 0.f);
                float h0 = (y0 - mean) * rs * sG1[j] + sBe1[j];
                float h1 = (y1 - mean) * rs * sG1[j + 1] + sBe1[j + 1];
                __nv_bfloat16 a0 = __float2bfloat16(h0), a1 = __float2bfloat16(h1);
                __nv_bfloat16 b0 = __float2bfloat16(h0 - __bfloat162float(a0));
                __nv_bfloat16 b1 = __float2bfloat16(h1 - __bfloat162float(a1));
                uint32_t hiw = (uint32_t)__bfloat16_as_ushort(a0) | ((uint32_t)__bfloat16_as_ushort(a1) << 16);
                uint32_t low = (uint32_t)__bfloat16_as_ushort(b0) | ((uint32_t)__bfloat16_as_ushort(b1) << 16);
                uint32_t off = (uint32_t)(tA * PK + j) * 2;
                *(uint32_t*)(sm + SM_AHI + off) = hiw;
                *(uint32_t*)(sm + SM_ALO + off) = low;
            }
        }
        __syncthreads();

        float c[64];
#pragma unroll
        for (int u = 0; u < 64; u++) c[u] = 0.f;

        uint32_t aoff = (uint32_t)((m0 + (lane & 15)) * PK + (lane >> 4) * 8) * 2;
        uint32_t brow = (uint32_t)(((lane & 16) >> 1) + (lane & 7));
        uint32_t bk   = (uint32_t)(((lane >> 3) & 1) * 8);

#pragma unroll
        for (int kk = 0; kk < 8; kk++) {
            uint32_t ah[4], al[4];
            uint32_t ka = aoff + (uint32_t)(kk * 16) * 2;
            ldsm_x4(ah[0], ah[1], ah[2], ah[3], smb + SM_AHI + ka);
            ldsm_x4(al[0], al[1], al[2], al[3], smb + SM_ALO + ka);
#pragma unroll
            for (int jp = 0; jp < 8; jp++) {
                uint32_t boff = (uint32_t)((jp * 16 + brow) * PK + kk * 16 + bk) * 2;
                uint32_t bh4[4], bl4[4];
                ldsm_x4(bh4[0], bh4[1], bh4[2], bh4[3], smb + SM_BHI + boff);
                ldsm_x4(bl4[0], bl4[1], bl4[2], bl4[3], smb + SM_BLO + boff);
                float* ca = c + (jp * 2) * 4;
                float* cb = c + (jp * 2 + 1) * 4;
                mma_bf16(ca, ah, bh4[0], bh4[1]);
                mma_bf16(ca, al, bh4[0], bh4[1]);
                mma_bf16(ca, ah, bl4[0], bl4[1]);
                mma_bf16(cb, ah, bh4[2], bh4[3]);
                mma_bf16(cb, al, bh4[2], bh4[3]);
                mma_bf16(cb, ah, bl4[2], bl4[3]);
            }
        }

        float m0v = sMask[r0], m1v = sMask[r1];
        float sum0 = 0.f, ss0 = 0.f, sum1 = 0.f, ss1 = 0.f;
#pragma unroll
        for (int jt = 0; jt < 16; jt++) {
            int col = jt * 8 + (lane & 3) * 2;
            float bh0 = sBh[col], bh1 = sBh[col + 1];
            float e0 = fmaxf(c[jt * 4 + 0] + bh0, 0.f);
            float e1 = fmaxf(c[jt * 4 + 1] + bh1, 0.f);
            float e2 = fmaxf(c[jt * 4 + 2] + bh0, 0.f);
            float e3 = fmaxf(c[jt * 4 + 3] + bh1, 0.f);
            sum0 += e0 + e1; ss0 += e0 * e0 + e1 * e1;
            sum1 += e2 + e3; ss1 += e2 * e2 + e3 * e3;
        }
#pragma unroll
        for (int o = 1; o <= 2; o <<= 1) {
            sum0 += __shfl_xor_sync(0xffffffffu, sum0, o);
            ss0  += __shfl_xor_sync(0xffffffffu, ss0, o);
            sum1 += __shfl_xor_sync(0xffffffffu, sum1, o);
            ss1  += __shfl_xor_sync(0xffffffffu, ss1, o);
        }
        float mean0 = sum0 * (1.f / 128.f);
        float rs0 = rsqrtf(ss0 * (1.f / 128.f) - mean0 * mean0 + 1e-5f) * m0v;
        float mean1 = sum1 * (1.f / 128.f);
        float rs1 = rsqrtf(ss1 * (1.f / 128.f) - mean1 * mean1 + 1e-5f) * m1v;
#pragma unroll
        for (int jt = 0; jt < 16; jt++) {
            int col = jt * 8 + (lane & 3) * 2;
            float bh0 = sBh[col], bh1 = sBh[col + 1];
            float e0 = fmaxf(c[jt * 4 + 0] + bh0, 0.f);
            float e1 = fmaxf(c[jt * 4 + 1] + bh1, 0.f);
            float e2 = fmaxf(c[jt * 4 + 2] + bh0, 0.f);
            float e3 = fmaxf(c[jt * 4 + 3] + bh1, 0.f);
            accS[jt * 4 + 0] += (e0 - mean0) * rs0;
            accS[jt * 4 + 1] += (e1 - mean0) * rs0;
            accS[jt * 4 + 2] += (e2 - mean1) * rs1;
            accS[jt * 4 + 3] += (e3 - mean1) * rs1;
        }
        cnt0 += m0v; cnt1 += m1v;
    }

    unsigned pbase = OFF_PART + (unsigned)(chunk * 32 + b) * 16384u;
#pragma unroll
    for (int jt = 0; jt < 16; jt++) {
        int col = jt * 8 + (lane & 3) * 2;
        *(float2*)(g_scratch + pbase + (unsigned)r0 * 128u + col) = make_float2(accS[jt * 4 + 0], accS[jt * 4 + 1]);
        *(float2*)(g_scratch + pbase + (unsigned)r1 * 128u + col) = make_float2(accS[jt * 4 + 2], accS[jt * 4 + 3]);
    }
    if ((lane & 3) == 0) {
        unsigned cbase = OFF_CNT + (unsigned)(chunk * 32 + b) * 128u;
        g_scratch[cbase + r0] = cnt0;
        g_scratch[cbase + r1] = cnt1;
    }
}

// ---------------------------------------------------------------------------
// Kernel 2b: combine partials + outer-LN affine -> x0
// ---------------------------------------------------------------------------
__global__ void k_combine(const float* __restrict__ gh, const float* __restrict__ beh) {
    int bt = blockIdx.x;
    int j = threadIdx.x;
    float v = 0.f, c = 0.f;
#pragma unroll
    for (int q = 0; q < 4; q++) {
        v += g_scratch[OFF_PART + (unsigned)q * 524288u + (unsigned)bt * 128u + j];
        c += g_scratch[OFF_CNT + (unsigned)q * 4096u + bt];
    }
    g_scratch[OFF_X0 + (unsigned)bt * 128u + j] = gh[j] * v + beh[j] * c;
}

// ---------------------------------------------------------------------------
// Kernel 3 (HMMA proj, B fragments from global): block tile 64 rows x 256 cols
// (blockIdx.y selects matrix 0=Q 1=K 2=V 3=S). No B staging, no k-loop syncs.
// ---------------------------------------------------------------------------
template <int HIN>
__global__ void __launch_bounds__(256, 1)
k_proj_mma(unsigned xoff, unsigned wfoff,
           const float* __restrict__ bq, const float* __restrict__ bk,
           const float* __restrict__ bv, const float* __restrict__ bs) {
    extern __shared__ char sm[];
    constexpr int PJ = HIN + 8;
    constexpr int XHI = 0;
    constexpr int XLO = XHI + 64 * PJ * 2;
    constexpr int KT = HIN / 16;
    constexpr int RSH = (HIN == 128) ? 7 : 8;

    uint32_t smb = smem_u32(sm);
    int tid = threadIdx.x, lane = tid & 31, wid = tid >> 5;
    int r0 = blockIdx.x * 64;
    int my = blockIdx.y;
    const float* bias = (my == 0) ? bq : (my == 1) ? bk : (my == 2) ? bv : bs;
    unsigned outoff   = (my == 0) ? OFF_Q : (my == 1) ? OFF_K : (my == 2) ? OFF_V : OFF_S;
    const float* x = g_scratch + xoff;
    const uint4* BF = (const uint4*)(g_scratch + wfoff + (unsigned)my * (32u * KT * 32u * 4u));

    // Load X tile [64 x HIN] hi/lo into smem
    for (int idx = tid; idx < 64 * HIN; idx += 256) {
        int r = idx >> RSH, k = idx & (HIN - 1);
        float v = x[(unsigned)(r0 + r) * HIN + k];
        __nv_bfloat16 h = __float2bfloat16(v);
        __nv_bfloat16 l = __float2bfloat16(v - __bfloat162float(h));
        *(__nv_bfloat16*)(sm + XHI + (r * PJ + k) * 2) = h;
        *(__nv_bfloat16*)(sm + XLO + (r * PJ + k) * 2) = l;
    }
    __syncthreads();

    int mrow = wid & 3, ncol = wid >> 2;   // 4 row-groups x 2 col-groups
    int m0 = mrow * 16;
    uint32_t aoff = (uint32_t)((m0 + (lane & 15)) * PJ + (lane >> 4) * 8) * 2;

    float c[64];
#pragma unroll
    for (int u = 0; u < 64; u++) c[u] = 0.f;

#pragma unroll
    for (int kk = 0; kk < KT; kk++) {
        uint32_t ah[4], al[4];
        uint32_t ka = aoff + (uint32_t)(kk * 16) * 2;
        ldsm_x4(ah[0], ah[1], ah[2], ah[3], smb + XHI + ka);
        ldsm_x4(al[0], al[1], al[2], al[3], smb + XLO + ka);
#pragma unroll
        for (int jp = 0; jp < 16; jp++) {
            int nt = ncol * 16 + jp;
            uint4 f = BF[(unsigned)(nt * KT + kk) * 32u + lane];
            float* cj = c + jp * 4;
            mma_bf16(cj, ah, f.x, f.y);
            mma_bf16(cj, al, f.x, f.y);
            mma_bf16(cj, ah, f.z, f.w);
        }
    }

    // Epilogue: + bias, store
    int rA = r0 + m0 + (lane >> 2);
    int rB = rA + 8;
#pragma unroll
    for (int jp = 0; jp < 16; jp++) {
        int col = ncol * 128 + jp * 8 + (lane & 3) * 2;
        float b0 = bias[col], b1 = bias[col + 1];
        *(float2*)(g_scratch + outoff + (unsigned)rA * HD + col) =
            make_float2(c[jp * 4 + 0] + b0, c[jp * 4 + 1] + b1);
        *(float2*)(g_scratch + outoff + (unsigned)rB * HD + col) =
            make_float2(c[jp * 4 + 2] + b0, c[jp * 4 + 3] + b1);
    }
}

// ---------------------------------------------------------------------------
// Kernel 4: attention (batched reductions) — unchanged from Round 4
// ---------------------------------------------------------------------------
#define TB 8
__global__ void __launch_bounds__(128)
k_attn(const float* __restrict__ adj, const float* __restrict__ we, unsigned outoff) {
    __shared__ float sK[128][65];
    __shared__ float sQ[TB][64];
    __shared__ float sW[TB][128];
    __shared__ float sB[TB];
    __shared__ float sQE[TB];
    __shared__ float redM[4][TB], redS[4][TB], redWA[4][TB];
    __shared__ float sPart[TB][64];

    int b = blockIdx.z, h = blockIdx.y, t0 = blockIdx.x * TB;
    int tid = threadIdx.x, lane = tid & 31, wid = tid >> 5;
    const float* q = g_scratch + OFF_Q;
    const float* k = g_scratch + OFF_K;
    const float* v = g_scratch + OFF_V;
    const float* skip = g_scratch + OFF_S;
    float* xout = g_scratch + outoff;

    for (int idx = tid; idx < 128 * 64; idx += 128) {
        int s = idx >> 6, d = idx & 63;
        sK[s][d] = k[((b * NN + s) * NHEADS + h) * DH + d];
    }
    for (int idx = tid; idx < TB * 64; idx += 128) {
        int u = idx >> 6, d = idx & 63;
        sQ[u][d] = q[((b * NN + t0 + u) * NHEADS + h) * DH + d];
    }
    __syncthreads();

    {
        int u = tid >> 4, l = tid & 15;
        float p = 0.f;
#pragma unroll
        for (int c = 0; c < 4; c++) { int d = l + 16 * c; p += sQ[u][d] * we[h * DH + d]; }
        unsigned gm = 0xFFFFu << (tid & 16);
#pragma unroll
        for (int o = 8; o >= 1; o >>= 1) p += __shfl_xor_sync(gm, p, o);
        if (l == 0) sQE[u] = p;
    }
    __syncthreads();

    const float scale = 0.125f;
    int s = tid;

    float4 a0 = *(const float4*)(adj + (unsigned)(b * NN + s) * NN + t0);
    float4 a1 = *(const float4*)(adj + (unsigned)(b * NN + s) * NN + t0 + 4);
    float av8[TB] = {a0.x, a0.y, a0.z, a0.w, a1.x, a1.y, a1.z, a1.w};
    float m8[TB], dot[TB];
#pragma unroll
    for (int u = 0; u < TB; u++) {
        bool m = (av8[u] > 0.f) && (av8[u] < 1.0f);
        m8[u] = m ? 1.f : 0.f;
        av8[u] = m ? av8[u] : 0.f;
        dot[u] = 0.f;
    }
#pragma unroll 8
    for (int d = 0; d < 64; d++) {
        float kv = sK[s][d];
#pragma unroll
        for (int u = 0; u < TB; u++) dot[u] += kv * sQ[u][d];
    }
    float lg[TB];
#pragma unroll
    for (int u = 0; u < TB; u++)
        lg[u] = (m8[u] > 0.f) ? (dot[u] + av8[u] * sQE[u]) * scale : -1e30f;

#pragma unroll
    for (int u = 0; u < TB; u++) {
        float mx = lg[u];
#pragma unroll
        for (int o = 16; o >= 1; o >>= 1) mx = fmaxf(mx, __shfl_xor_sync(0xffffffffu, mx, o));
        if (lane == 0) redM[wid][u] = mx;
    }
    __syncthreads();

    float w8[TB], wa8[TB];
#pragma unroll
    for (int u = 0; u < TB; u++) {
        float mx = fmaxf(fmaxf(redM[0][u], redM[1][u]), fmaxf(redM[2][u], redM[3][u]));
        float w = (m8[u] > 0.f) ? __expf(lg[u] - mx) : 0.f;
        w8[u] = w; wa8[u] = w * av8[u];
    }
#pragma unroll
    for (int u = 0; u < TB; u++) {
        float sw = w8[u], swa = wa8[u];
#pragma unroll
        for (int o = 16; o >= 1; o >>= 1) {
            sw  += __shfl_xor_sync(0xffffffffu, sw, o);
            swa += __shfl_xor_sync(0xffffffffu, swa, o);
        }
        if (lane == 0) { redS[wid][u] = sw; redWA[wid][u] = swa; }
    }
    __syncthreads();

#pragma unroll
    for (int u = 0; u < TB; u++) {
        float den = redS[0][u] + redS[1][u] + redS[2][u] + redS[3][u];
        float SWA = redWA[0][u] + redWA[1][u] + redWA[2][u] + redWA[3][u];
        float inv = 1.f / fmaxf(den, 1e-16f);
        sW[u][s] = w8[u] * inv;
        if (tid == u) sB[u] = SWA * inv;
    }
    __syncthreads();

    int d = tid & 63, half = tid >> 6;
    float o8[TB];
#pragma unroll
    for (int u = 0; u < TB; u++) o8[u] = 0.f;
    for (int s2 = half * 64; s2 < half * 64 + 64; s2++) {
        float vv = v[((b * NN + s2) * NHEADS + h) * DH + d];
#pragma unroll
        for (int u = 0; u < TB; u++) o8[u] += sW[u][s2] * vv;
    }
    if (half == 1) {
#pragma unroll
        for (int u = 0; u < TB; u++) sPart[u][d] = o8[u];
    }
    __syncthreads();
    if (half == 0) {
        float wev = we[h * DH + d];
#pragma unroll
        for (int u = 0; u < TB; u++) {
            int t = t0 + u;
            unsigned idx = (unsigned)(b * NN + t) * HD + h * DH + d;
            float res = o8[u] + sPart[u][d] + sB[u] * wev + skip[idx];
            xout[idx] = fmaxf(res, 0.f);
        }
    }
}

// ---------------------------------------------------------------------------
// Kernel 5: gather agent rows
// ---------------------------------------------------------------------------
__global__ void k_gather(const int* __restrict__ agent, float* __restrict__ out) {
    int b = blockIdx.x, j = threadIdx.x;
    out[b * HD + j] = g_scratch[OFF_X2 + (unsigned)(b * NN + agent[b]) * HD + j];
}

// ---------------------------------------------------------------------------
extern "C" void kernel_launch(void* const* d_in, const int* in_sizes, int n_in,
                              void* d_out, int out_size) {
    const float* node_feat = (const float*)d_in[0];
    const int*   entity_type = (const int*)d_in[1];
    const float* adj = (const float*)d_in[2];
    const int*   agent_id = (const int*)d_in[3];
    const float* emb = (const float*)d_in[4];
    const float* W1 = (const float*)d_in[5];
    const float* b1 = (const float*)d_in[6];
    const float* g1 = (const float*)d_in[7];
    const float* be1 = (const float*)d_in[8];
    const float* Wh = (const float*)d_in[9];
    const float* bh = (const float*)d_in[10];
    const float* gh = (const float*)d_in[11];
    const float* beh = (const float*)d_in[12];
    const float* Wq1 = (const float*)d_in[13];
    const float* bq1 = (const float*)d_in[14];
    const float* Wk1 = (const float*)d_in[15];
    const float* bk1 = (const float*)d_in[16];
    const float* Wv1 = (const float*)d_in[17];
    const float* bv1 = (const float*)d_in[18];
    const float* We1 = (const float*)d_in[19];
    const float* Ws1 = (const float*)d_in[20];
    const float* bs1 = (const float*)d_in[21];
    const float* Wq2 = (const float*)d_in[22];
    const float* bq2 = (const float*)d_in[23];
    const float* Wk2 = (const float*)d_in[24];
    const float* bk2 = (const float*)d_in[25];
    const float* Wv2 = (const float*)d_in[26];
    const float* bv2 = (const float*)d_in[27];
    const float* We2 = (const float*)d_in[28];
    const float* Ws2 = (const float*)d_in[29];
    const float* bs2 = (const float*)d_in[30];

    constexpr int PROJ128_SMEM = 2 * 64 * 136 * 2;   // 34816
    constexpr int PROJ256_SMEM = 2 * 64 * 264 * 2;   // 67584

    cudaFuncSetAttribute(k_embed_mma, cudaFuncAttributeMaxDynamicSharedMemorySize, EMB_SMEM);
    cudaFuncSetAttribute(k_proj_mma<128>, cudaFuncAttributeMaxDynamicSharedMemorySize, PROJ128_SMEM);
    cudaFuncSetAttribute(k_proj_mma<256>, cudaFuncAttributeMaxDynamicSharedMemorySize, PROJ256_SMEM);

    k_wsplit<<<384, 256>>>(Wq1, Wk1, Wv1, Ws1, Wq2, Wk2, Wv2, Ws2);
    k_base<<<BB * NN, 128>>>(node_feat, entity_type, emb, W1, b1);
    k_embed_mma<<<dim3(4, BB), 256, EMB_SMEM>>>(adj, W1, g1, be1, Wh, bh);
    k_combine<<<BB * NN, 128>>>(gh, beh);

    k_proj_mma<128><<<dim3(64, 4), 256, PROJ128_SMEM>>>(OFF_X0, OFF_WF, bq1, bk1, bv1, bs1);
    k_attn<<<dim3(NN / TB, NHEADS, BB), 128>>>(adj, We1, OFF_X1);

    k_proj_mma<256><<<dim3(64, 4), 256, PROJ256_SMEM>>>(OFF_X1, OFF_WF + 131072u, bq2, bk2, bv2, bs2);
    k_attn<<<dim3(NN / TB, NHEADS, BB), 128>>>(adj, We2, OFF_X2);

    k_gather<<<BB, 256>>>(agent_id, (float*)d_out);
}